// round 14
// baseline (speedup 1.0000x reference)
#include <cuda_runtime.h>
#include <cuda_bf16.h>
#include <math.h>
#include <stdint.h>

// Problem constants
#define NB 16
#define T1 400
#define T2 600
#define DIM 1024
#define T2Q (T2 / 4)          // 150 packed-choice bytes per row
#define SPLIT 192             // DTW backtrack staging split row
#define RPL 16                // DTW rows per lane
#define NLANES 25             // 25 * 16 = 400 rows
#define BIGF 1e30f

// ---------------------------------------------------------------------------
// Device scratch (no allocations allowed)
// ---------------------------------------------------------------------------
__device__ float g_D[NB * T1 * T2];            // distance matrix, ROW-major [b][i][j]
__device__ float g_na[NB * T1];
__device__ float g_nb[NB * T2];
__device__ int   g_lo[NB * T2];
__device__ int   g_hi[NB * T2];
__device__ unsigned char g_ch[NB * T2Q * T1];  // 2-bit DP choices [b][jq][i]

// ---------------------------------------------------------------------------
// Kernel 0: dummy — keep the ncu-profiled launch (index 3) on dtw_kernel.
// ---------------------------------------------------------------------------
__global__ void dummy_kernel() {}

// ---------------------------------------------------------------------------
// Kernel 1: squared norms. One warp per row.
// ---------------------------------------------------------------------------
__global__ void norm_kernel(const float* __restrict__ T, const float* __restrict__ S) {
    int warp = (blockIdx.x * blockDim.x + threadIdx.x) >> 5;
    int lane = threadIdx.x & 31;
    const int NT = NB * T1;
    const int NS = NB * T2;
    if (warp >= NT + NS) return;
    const float* src;
    float* dst;
    if (warp < NT) { src = T + (size_t)warp * DIM;        dst = g_na + warp; }
    else           { src = S + (size_t)(warp - NT) * DIM; dst = g_nb + (warp - NT); }
    float s = 0.f;
#pragma unroll
    for (int it = 0; it < DIM / 128; it++) {
        float4 v = *(const float4*)(src + (size_t)(lane + it * 32) * 4);
        s += v.x * v.x + v.y * v.y + v.z * v.z + v.w * v.w;
    }
#pragma unroll
    for (int o = 16; o; o >>= 1) s += __shfl_xor_sync(0xFFFFFFFFu, s, o);
    if (lane == 0) *dst = s;
}

// ---------------------------------------------------------------------------
// Kernel 2: batched SIMT GEMM + distance epilogue -> ROW-major D.
// R6 mainloop + row-major coalesced epilogue (measured ~344us in R10).
// ---------------------------------------------------------------------------
#define BM 64
#define BN 128
#define BK 16
#define NKT (DIM / BK)   // 64

__global__ __launch_bounds__(256)
void gemm_dist_kernel(const float* __restrict__ A, const float* __restrict__ B) {
    int b  = blockIdx.z;
    int m0 = blockIdx.y * BM;
    int n0 = blockIdx.x * BN;
    const float* Ab = A + (size_t)b * T1 * DIM;
    const float* Bb = B + (size_t)b * T2 * DIM;

    __shared__ float As[2][BK][BM];
    __shared__ float Bs[2][BK][BN];

    int tid = threadIdx.x;
    int tx = tid & 15;
    int ty = tid >> 4;

    float acc[4][8];
#pragma unroll
    for (int i = 0; i < 4; i++)
#pragma unroll
        for (int j = 0; j < 8; j++) acc[i][j] = 0.f;

    int arow = tid >> 2;
    int acol = (tid & 3) << 2;
    bool aok = (m0 + arow) < T1;
    const float* aptr = Ab + (size_t)(m0 + arow) * DIM + acol;

    int brow0 = tid >> 2;
    int brow1 = (tid + 256) >> 2;
    int bcol  = (tid & 3) << 2;
    bool bok0 = (n0 + brow0) < T2;
    bool bok1 = (n0 + brow1) < T2;
    const float* bptr0 = Bb + (size_t)(n0 + brow0) * DIM + bcol;
    const float* bptr1 = Bb + (size_t)(n0 + brow1) * DIM + bcol;

    const float4 Z = make_float4(0.f, 0.f, 0.f, 0.f);
    float4 sa, sb0, sb1;

    sa  = aok  ? *(const float4*)(aptr)  : Z;
    sb0 = bok0 ? *(const float4*)(bptr0) : Z;
    sb1 = bok1 ? *(const float4*)(bptr1) : Z;
    As[0][acol + 0][arow] = sa.x;  As[0][acol + 1][arow] = sa.y;
    As[0][acol + 2][arow] = sa.z;  As[0][acol + 3][arow] = sa.w;
    Bs[0][bcol + 0][brow0] = sb0.x; Bs[0][bcol + 1][brow0] = sb0.y;
    Bs[0][bcol + 2][brow0] = sb0.z; Bs[0][bcol + 3][brow0] = sb0.w;
    Bs[0][bcol + 0][brow1] = sb1.x; Bs[0][bcol + 1][brow1] = sb1.y;
    Bs[0][bcol + 2][brow1] = sb1.z; Bs[0][bcol + 3][brow1] = sb1.w;
    __syncthreads();

    for (int kt = 0; kt < NKT; kt++) {
        int c = kt & 1;
        if (kt + 1 < NKT) {
            const float* ap = aptr + (kt + 1) * BK;
            sa  = aok  ? *(const float4*)(ap) : Z;
            sb0 = bok0 ? *(const float4*)(bptr0 + (kt + 1) * BK) : Z;
            sb1 = bok1 ? *(const float4*)(bptr1 + (kt + 1) * BK) : Z;
        }

#pragma unroll
        for (int k = 0; k < BK; k++) {
            float4 af  = *(const float4*)&As[c][k][ty * 4];
            float4 bf0 = *(const float4*)&Bs[c][k][tx * 8];
            float4 bf1 = *(const float4*)&Bs[c][k][tx * 8 + 4];
            float ar[4] = { af.x, af.y, af.z, af.w };
            float br[8] = { bf0.x, bf0.y, bf0.z, bf0.w, bf1.x, bf1.y, bf1.z, bf1.w };
#pragma unroll
            for (int i = 0; i < 4; i++)
#pragma unroll
                for (int j = 0; j < 8; j++)
                    acc[i][j] = fmaf(ar[i], br[j], acc[i][j]);
        }

        if (kt + 1 < NKT) {
            int nc = c ^ 1;
            As[nc][acol + 0][arow] = sa.x;  As[nc][acol + 1][arow] = sa.y;
            As[nc][acol + 2][arow] = sa.z;  As[nc][acol + 3][arow] = sa.w;
            Bs[nc][bcol + 0][brow0] = sb0.x; Bs[nc][bcol + 1][brow0] = sb0.y;
            Bs[nc][bcol + 2][brow0] = sb0.z; Bs[nc][bcol + 3][brow0] = sb0.w;
            Bs[nc][bcol + 0][brow1] = sb1.x; Bs[nc][bcol + 1][brow1] = sb1.y;
            Bs[nc][bcol + 2][brow1] = sb1.z; Bs[nc][bcol + 3][brow1] = sb1.w;
            __syncthreads();
        }
    }

    int n = n0 + tx * 8;
    if (n < T2) {
        float nb0 = g_nb[b * T2 + n + 0], nb1 = g_nb[b * T2 + n + 1];
        float nb2 = g_nb[b * T2 + n + 2], nb3 = g_nb[b * T2 + n + 3];
        float nb4 = g_nb[b * T2 + n + 4], nb5 = g_nb[b * T2 + n + 5];
        float nb6 = g_nb[b * T2 + n + 6], nb7 = g_nb[b * T2 + n + 7];
#pragma unroll
        for (int i = 0; i < 4; i++) {
            int m = m0 + ty * 4 + i;
            if (m >= T1) continue;
            float nam = g_na[b * T1 + m];
            float4 o0, o1;
            o0.x = sqrtf(fmaxf(nam + nb0 - 2.f * acc[i][0], 0.f));
            o0.y = sqrtf(fmaxf(nam + nb1 - 2.f * acc[i][1], 0.f));
            o0.z = sqrtf(fmaxf(nam + nb2 - 2.f * acc[i][2], 0.f));
            o0.w = sqrtf(fmaxf(nam + nb3 - 2.f * acc[i][3], 0.f));
            o1.x = sqrtf(fmaxf(nam + nb4 - 2.f * acc[i][4], 0.f));
            o1.y = sqrtf(fmaxf(nam + nb5 - 2.f * acc[i][5], 0.f));
            o1.z = sqrtf(fmaxf(nam + nb6 - 2.f * acc[i][6], 0.f));
            o1.w = sqrtf(fmaxf(nam + nb7 - 2.f * acc[i][7], 0.f));
            float* dst = g_D + ((size_t)(b * T1 + m)) * T2 + n;
            *(float4*)(dst)     = o0;
            *(float4*)(dst + 4) = o1;
        }
    }
}

// ---------------------------------------------------------------------------
// Kernel 3: warp-per-batch register DTW, fully predicated, FLOAT2 D buffers
// (halves buffer registers vs R11's float4 -> target: no spills). Cell DAG,
// masks, tie-breaks and choice packing byte-identical to passing R10/R11.
// comp/par are static after the x4 unroll: s=(U-rr)&3, comp=s&1, par=s>>1;
// since kb%4==0 and i0%4==0, j mod 4 == s, so comp==j&1 and par==(j>>1)&1.
// Buffer par holds columns (j, j+1); at comp==0 prefetch (j+2, j+3) into
// par^1 (consumed 2 diagonals later -> latency slack; D is L2-resident).
// All float2 accesses are 8B-aligned (row stride 600 floats, j even at loads).
// ---------------------------------------------------------------------------
#define DTW_STEP(PREV, PPW, U) do {                                              \
    float sprev = __shfl_up_sync(0xFFFFFFFFu, PREV[RPL - 1], 1);                 \
    float spp   = __shfl_up_sync(0xFFFFFFFFu, PPW[RPL - 1], 1);                  \
    int e = kb + (U) - i0;                                                       \
_Pragma("unroll")                                                                \
    for (int rr_ = RPL - 1; rr_ >= 0; rr_--) {                                   \
        const int s_   = ((U) - rr_) & 3;                                        \
        const int comp = s_ & 1;                                                 \
        const int par  = (s_ >> 1) & 1;                                          \
        int j = e - rr_;                                                         \
        int i = i0 + rr_;                                                        \
        if (comp == 0) {                                                         \
            bool ldok = act & ((unsigned)j <= (unsigned)(T2 - 4));               \
            if (ldok)                                                            \
                dbuf[par ^ 1][rr_] = *(const float2*)(Db + (size_t)i * T2 + j + 2); \
        }                                                                        \
        float d = comp ? dbuf[par][rr_].y : dbuf[par][rr_].x;                    \
        bool valid = act & ((unsigned)j < (unsigned)T2);                         \
        float cu_ = (rr_ == 0) ? sprev : PREV[(rr_ > 0) ? rr_ - 1 : 0];          \
        float cd_ = (rr_ == 0) ? spp   : PPW[(rr_ > 0) ? rr_ - 1 : 0];           \
        float cl_ = PREV[rr_];                                                   \
        float cuv = (i > 0) ? cu_ : BIGF;                                        \
        float clv = (j > 0) ? cl_ : BIGF;                                        \
        float cdv = (i > 0 && j > 0) ? cd_ : BIGF;                               \
        float m3 = fminf(fminf(cuv, clv), cdv);                                  \
        float rrv = d + ((i == 0 && j == 0) ? 0.f : m3);                         \
        unsigned int c = (cdv <= cuv && cdv <= clv) ? 0u : ((cuv <= clv) ? 1u : 2u); \
        PPW[rr_] = valid ? rrv : PPW[rr_];                                       \
        unsigned int newc = cacc[rr_] | (c << ((j & 3) * 2));                    \
        cacc[rr_] = valid ? (((j & 3) == 3) ? 0u : newc) : cacc[rr_];            \
        if (valid && (j & 3) == 3)                                               \
            chb[(j >> 2) * T1 + i] = (unsigned char)newc;                        \
    }                                                                            \
} while (0)

__global__ __launch_bounds__(128, 1)
void dtw_kernel() {
    __shared__ int slo[T2];
    __shared__ int shi[T2];
    __shared__ unsigned char chS[(T1 - SPLIT) * T2Q];  // 31200 B, reused for bottom half
    __shared__ int s_pi, s_pj;

    int b = blockIdx.x;
    int tid = threadIdx.x;
    const float* Db = g_D + (size_t)b * T1 * T2;
    unsigned char* chb = g_ch + (size_t)b * T2Q * T1;

    if (tid < 32) {
        int lane = tid;
        bool act = (lane < NLANES);
        int i0 = (act ? lane : 0) * RPL;   // clamp inactive lanes for preload

        float rA[RPL], rB[RPL];
        float2 dbuf[2][RPL];
        unsigned int cacc[RPL];
#pragma unroll
        for (int r = 0; r < RPL; r++) {
            rA[r] = 0.f; rB[r] = 0.f; cacc[r] = 0u;
            dbuf[0][r] = make_float2(0.f, 0.f);
            dbuf[1][r] = make_float2(0.f, 0.f);
        }
        // preload block j=0,1 per row into buffer 0
#pragma unroll
        for (int r = 0; r < RPL; r++)
            dbuf[0][r] = *(const float2*)(Db + (size_t)(i0 + r) * T2);

        i0 = lane * RPL;   // true row base for index math

        // k = kb+U; (j & 3) == ((U - rr) & 3) since kb%4==0 and i0%4==0.
        for (int kb = 0; kb < 1000; kb += 4) {
            DTW_STEP(rA, rB, 0);
            DTW_STEP(rB, rA, 1);
            DTW_STEP(rA, rB, 2);
            DTW_STEP(rB, rA, 3);
        }
    }
    __syncthreads();

    // --- Stage TOP choice rows [SPLIT..T1) into smem
    {
        const int RT = T1 - SPLIT;
        for (int idx = tid; idx < T2Q * RT; idx += blockDim.x) {
            int jq = idx / RT;
            int o  = idx - jq * RT;
            chS[idx] = chb[jq * T1 + SPLIT + o];
        }
    }
    __syncthreads();

    // --- Backtrack phase A (rows >= SPLIT), all-smem chase
    if (tid == 0) {
        const int RT = T1 - SPLIT;
        int pi = T1 - 1, pj = T2 - 1;
        shi[pj] = pi;
        while (pi >= SPLIT) {
            slo[pj] = pi;
            int c = (chS[(pj >> 2) * RT + (pi - SPLIT)] >> ((pj & 3) * 2)) & 3;
            int ni = (c <= 1) ? pi - 1 : pi;
            int nj = (c != 1) ? pj - 1 : pj;
            if (nj != pj) shi[nj] = ni;
            pi = ni; pj = nj;
        }
        s_pi = pi; s_pj = pj;
    }
    __syncthreads();

    // --- Stage BOTTOM choice rows [0..SPLIT)
    for (int idx = tid; idx < T2Q * SPLIT; idx += blockDim.x) {
        int jq = idx / SPLIT;
        int o  = idx - jq * SPLIT;
        chS[idx] = chb[jq * T1 + o];
    }
    __syncthreads();

    // --- Backtrack phase B (rows < SPLIT)
    if (tid == 0) {
        int pi = s_pi, pj = s_pj;
        while (true) {
            slo[pj] = pi;
            if (pi == 0 && pj == 0) break;
            int c = (chS[(pj >> 2) * SPLIT + pi] >> ((pj & 3) * 2)) & 3;
            int ni = (c <= 1) ? pi - 1 : pi;
            int nj = (c != 1) ? pj - 1 : pj;
            if (nj != pj) shi[nj] = ni;
            pi = ni; pj = nj;
        }
    }
    __syncthreads();

    for (int j = tid; j < T2; j += blockDim.x) {
        g_lo[b * T2 + j] = slo[j];
        g_hi[b * T2 + j] = shi[j];
    }
}

// ---------------------------------------------------------------------------
// Kernel 4: expansion — out[b][j][:] = sum_{i=lo..hi} teacher[b][i][:]
// ---------------------------------------------------------------------------
__global__ __launch_bounds__(256)
void expand_kernel(const float* __restrict__ Tt, float* __restrict__ out) {
    int j = blockIdx.x;
    int b = blockIdx.y;
    int lo = g_lo[b * T2 + j];
    int hi = g_hi[b * T2 + j];
    int d4 = threadIdx.x;
    float4 acc = make_float4(0.f, 0.f, 0.f, 0.f);
    const float4* base = (const float4*)(Tt + (size_t)b * T1 * DIM);
    for (int i2 = lo; i2 <= hi; i2++) {
        float4 v = base[(size_t)i2 * (DIM / 4) + d4];
        acc.x += v.x; acc.y += v.y; acc.z += v.z; acc.w += v.w;
    }
    ((float4*)out)[(size_t)(b * T2 + j) * (DIM / 4) + d4] = acc;
}

// ---------------------------------------------------------------------------
// Launch — kernel launches only. Profiled launch = index 3 = dtw_kernel.
// ---------------------------------------------------------------------------
extern "C" void kernel_launch(void* const* d_in, const int* in_sizes, int n_in,
                              void* d_out, int out_size) {
    const float* teacher = (const float*)d_in[0];  // [16,400,1024]
    const float* student = (const float*)d_in[1];  // [16,600,1024]
    float* out = (float*)d_out;                    // [16,600,1024]

    dummy_kernel<<<1, 32>>>();

    {
        int nwarps = NB * (T1 + T2);
        int nblocks = (nwarps + 7) / 8;
        norm_kernel<<<nblocks, 256>>>(teacher, student);
    }

    {
        dim3 grid((T2 + BN - 1) / BN, (T1 + BM - 1) / BM, NB);
        gemm_dist_kernel<<<grid, 256>>>(teacher, student);
    }

    dtw_kernel<<<NB, 128>>>();

    {
        dim3 grid(T2, NB);
        expand_kernel<<<grid, 256>>>(teacher, out);
    }
}

// round 17
// speedup vs baseline: 1.5144x; 1.5144x over previous
#include <cuda_runtime.h>
#include <cuda_bf16.h>
#include <math.h>
#include <stdint.h>

// Problem constants
#define NB 16
#define T1 400
#define T2 600
#define DIM 1024
#define NDIAG (T1 + T2 - 1)   // 999
#define T2Q (T2 / 4)          // 150 packed-choice bytes per row
#define SPLIT 192             // DTW backtrack staging split row
#define PF 8                  // DTW D-prefetch depth (rotation)

// ---------------------------------------------------------------------------
// Device scratch (no allocations allowed)
// ---------------------------------------------------------------------------
__device__ float g_D[NB * T1 * T2];            // distance matrix, ROW-major [b][i][j]
__device__ float g_Dd[NB * NDIAG * T1];        // distance matrix, DIAG-major [b][k][i]
__device__ float g_na[NB * T1];
__device__ float g_nb[NB * T2];
__device__ int   g_lo[NB * T2];
__device__ int   g_hi[NB * T2];
__device__ unsigned char g_ch[NB * T2Q * T1];  // 2-bit DP choices [b][jq][i]

// ---------------------------------------------------------------------------
// Kernel 1: squared norms. One warp per row.
// ---------------------------------------------------------------------------
__global__ void norm_kernel(const float* __restrict__ T, const float* __restrict__ S) {
    int warp = (blockIdx.x * blockDim.x + threadIdx.x) >> 5;
    int lane = threadIdx.x & 31;
    const int NT = NB * T1;
    const int NS = NB * T2;
    if (warp >= NT + NS) return;
    const float* src;
    float* dst;
    if (warp < NT) { src = T + (size_t)warp * DIM;        dst = g_na + warp; }
    else           { src = S + (size_t)(warp - NT) * DIM; dst = g_nb + (warp - NT); }
    float s = 0.f;
#pragma unroll
    for (int it = 0; it < DIM / 128; it++) {
        float4 v = *(const float4*)(src + (size_t)(lane + it * 32) * 4);
        s += v.x * v.x + v.y * v.y + v.z * v.z + v.w * v.w;
    }
#pragma unroll
    for (int o = 16; o; o >>= 1) s += __shfl_xor_sync(0xFFFFFFFFu, s, o);
    if (lane == 0) *dst = s;
}

// ---------------------------------------------------------------------------
// Kernel 2: batched SIMT GEMM + distance epilogue -> ROW-major D.
// Verbatim from R10/R14 (best measured GEMM, ~300-350us).
// ---------------------------------------------------------------------------
#define BM 64
#define BN 128
#define BK 16
#define NKT (DIM / BK)   // 64

__global__ __launch_bounds__(256)
void gemm_dist_kernel(const float* __restrict__ A, const float* __restrict__ B) {
    int b  = blockIdx.z;
    int m0 = blockIdx.y * BM;
    int n0 = blockIdx.x * BN;
    const float* Ab = A + (size_t)b * T1 * DIM;
    const float* Bb = B + (size_t)b * T2 * DIM;

    __shared__ float As[2][BK][BM];
    __shared__ float Bs[2][BK][BN];

    int tid = threadIdx.x;
    int tx = tid & 15;
    int ty = tid >> 4;

    float acc[4][8];
#pragma unroll
    for (int i = 0; i < 4; i++)
#pragma unroll
        for (int j = 0; j < 8; j++) acc[i][j] = 0.f;

    int arow = tid >> 2;
    int acol = (tid & 3) << 2;
    bool aok = (m0 + arow) < T1;
    const float* aptr = Ab + (size_t)(m0 + arow) * DIM + acol;

    int brow0 = tid >> 2;
    int brow1 = (tid + 256) >> 2;
    int bcol  = (tid & 3) << 2;
    bool bok0 = (n0 + brow0) < T2;
    bool bok1 = (n0 + brow1) < T2;
    const float* bptr0 = Bb + (size_t)(n0 + brow0) * DIM + bcol;
    const float* bptr1 = Bb + (size_t)(n0 + brow1) * DIM + bcol;

    const float4 Z = make_float4(0.f, 0.f, 0.f, 0.f);
    float4 sa, sb0, sb1;

    sa  = aok  ? *(const float4*)(aptr)  : Z;
    sb0 = bok0 ? *(const float4*)(bptr0) : Z;
    sb1 = bok1 ? *(const float4*)(bptr1) : Z;
    As[0][acol + 0][arow] = sa.x;  As[0][acol + 1][arow] = sa.y;
    As[0][acol + 2][arow] = sa.z;  As[0][acol + 3][arow] = sa.w;
    Bs[0][bcol + 0][brow0] = sb0.x; Bs[0][bcol + 1][brow0] = sb0.y;
    Bs[0][bcol + 2][brow0] = sb0.z; Bs[0][bcol + 3][brow0] = sb0.w;
    Bs[0][bcol + 0][brow1] = sb1.x; Bs[0][bcol + 1][brow1] = sb1.y;
    Bs[0][bcol + 2][brow1] = sb1.z; Bs[0][bcol + 3][brow1] = sb1.w;
    __syncthreads();

    for (int kt = 0; kt < NKT; kt++) {
        int c = kt & 1;
        if (kt + 1 < NKT) {
            const float* ap = aptr + (kt + 1) * BK;
            sa  = aok  ? *(const float4*)(ap) : Z;
            sb0 = bok0 ? *(const float4*)(bptr0 + (kt + 1) * BK) : Z;
            sb1 = bok1 ? *(const float4*)(bptr1 + (kt + 1) * BK) : Z;
        }

#pragma unroll
        for (int k = 0; k < BK; k++) {
            float4 af  = *(const float4*)&As[c][k][ty * 4];
            float4 bf0 = *(const float4*)&Bs[c][k][tx * 8];
            float4 bf1 = *(const float4*)&Bs[c][k][tx * 8 + 4];
            float ar[4] = { af.x, af.y, af.z, af.w };
            float br[8] = { bf0.x, bf0.y, bf0.z, bf0.w, bf1.x, bf1.y, bf1.z, bf1.w };
#pragma unroll
            for (int i = 0; i < 4; i++)
#pragma unroll
                for (int j = 0; j < 8; j++)
                    acc[i][j] = fmaf(ar[i], br[j], acc[i][j]);
        }

        if (kt + 1 < NKT) {
            int nc = c ^ 1;
            As[nc][acol + 0][arow] = sa.x;  As[nc][acol + 1][arow] = sa.y;
            As[nc][acol + 2][arow] = sa.z;  As[nc][acol + 3][arow] = sa.w;
            Bs[nc][bcol + 0][brow0] = sb0.x; Bs[nc][bcol + 1][brow0] = sb0.y;
            Bs[nc][bcol + 2][brow0] = sb0.z; Bs[nc][bcol + 3][brow0] = sb0.w;
            Bs[nc][bcol + 0][brow1] = sb1.x; Bs[nc][bcol + 1][brow1] = sb1.y;
            Bs[nc][bcol + 2][brow1] = sb1.z; Bs[nc][bcol + 3][brow1] = sb1.w;
            __syncthreads();
        }
    }

    int n = n0 + tx * 8;
    if (n < T2) {
        float nb0 = g_nb[b * T2 + n + 0], nb1 = g_nb[b * T2 + n + 1];
        float nb2 = g_nb[b * T2 + n + 2], nb3 = g_nb[b * T2 + n + 3];
        float nb4 = g_nb[b * T2 + n + 4], nb5 = g_nb[b * T2 + n + 5];
        float nb6 = g_nb[b * T2 + n + 6], nb7 = g_nb[b * T2 + n + 7];
#pragma unroll
        for (int i = 0; i < 4; i++) {
            int m = m0 + ty * 4 + i;
            if (m >= T1) continue;
            float nam = g_na[b * T1 + m];
            float4 o0, o1;
            o0.x = sqrtf(fmaxf(nam + nb0 - 2.f * acc[i][0], 0.f));
            o0.y = sqrtf(fmaxf(nam + nb1 - 2.f * acc[i][1], 0.f));
            o0.z = sqrtf(fmaxf(nam + nb2 - 2.f * acc[i][2], 0.f));
            o0.w = sqrtf(fmaxf(nam + nb3 - 2.f * acc[i][3], 0.f));
            o1.x = sqrtf(fmaxf(nam + nb4 - 2.f * acc[i][4], 0.f));
            o1.y = sqrtf(fmaxf(nam + nb5 - 2.f * acc[i][5], 0.f));
            o1.z = sqrtf(fmaxf(nam + nb6 - 2.f * acc[i][6], 0.f));
            o1.w = sqrtf(fmaxf(nam + nb7 - 2.f * acc[i][7], 0.f));
            float* dst = g_D + ((size_t)(b * T1 + m)) * T2 + n;
            *(float4*)(dst)     = o0;
            *(float4*)(dst + 4) = o1;
        }
    }
}

// ---------------------------------------------------------------------------
// Kernel 2b: transpose row-major D -> diag-major Dd.
// 32x32 smem tiles (pad 34: diagonal reads hit stride 33 == 1 mod 32, no
// bank conflicts). Reads coalesced rows; writes <=32-float consecutive
// diagonal segments.
// ---------------------------------------------------------------------------
__global__ __launch_bounds__(256)
void transpose_diag_kernel() {
    __shared__ float t[32][34];
    int b  = blockIdx.z;
    int i0 = blockIdx.y * 32;
    int j0 = blockIdx.x * 32;
    int tid  = threadIdx.x;
    int lane = tid & 31;
    int w    = tid >> 5;

    const float* Db = g_D + (size_t)b * T1 * T2;
    float* Dd = g_Dd + (size_t)b * NDIAG * T1;

#pragma unroll
    for (int r = w; r < 32; r += 8) {
        int i = i0 + r, j = j0 + lane;
        t[r][lane] = (i < T1 && j < T2) ? Db[(size_t)i * T2 + j] : 0.f;
    }
    __syncthreads();

    for (int kl = w; kl < 63; kl += 8) {
        int k = i0 + j0 + kl;
        int ilo = k - (j0 + 31); if (ilo < i0) ilo = i0;
        int ihi = k - j0;        if (ihi > i0 + 31) ihi = i0 + 31;
        int i = ilo + lane;
        if (i <= ihi && i < T1 && (k - i) < T2)
            Dd[(size_t)k * T1 + i] = t[i - i0][k - i - j0];
    }
}

// ---------------------------------------------------------------------------
// Kernel 3: per-batch DTW DP — verbatim R7 (best measured DTW, ~272us):
// 416 threads, anti-diagonal wavefront over diag-major D, depth-8 ROTATION
// prefetch, then two-phase smem-staged backtrack.
// ---------------------------------------------------------------------------
__global__ __launch_bounds__(416)
void dtw_kernel() {
    __shared__ float sdiag[3 * T1];
    __shared__ int   slo[T2];
    __shared__ int   shi[T2];
    __shared__ unsigned char chS[(T1 - SPLIT) * T2Q];
    __shared__ int s_pi, s_pj;

    int b = blockIdx.x;
    int i = threadIdx.x;
    const float* Db = g_Dd + (size_t)b * NDIAG * T1;
    unsigned char* chb = g_ch + (size_t)b * T2Q * T1;

    unsigned int cacc = 0;
    bool rowok = (i < T1);

    float dpre[PF];
#pragma unroll
    for (int p = 0; p < PF; p++)
        dpre[p] = (rowok && p >= i && (p - i) < T2) ? Db[p * T1 + i] : 0.f;

    for (int kb = 0; kb < 1000; kb += PF) {
#pragma unroll
        for (int u = 0; u < PF; u++) {
            int k = kb + u;
            float d = dpre[u];
            int kp = k + PF;
            dpre[u] = (rowok && kp < NDIAG && kp >= i && (kp - i) < T2) ? Db[kp * T1 + i] : 0.f;

            float* cur = sdiag + (k % 3) * T1;
            float* prv = sdiag + ((k + 2) % 3) * T1;
            float* pp  = sdiag + ((k + 1) % 3) * T1;
            if (rowok && i <= k && (k - i) < T2) {
                int j = k - i;
                float r;
                unsigned int c;
                if (i == 0 && j == 0)      { r = d; c = 0u; }
                else if (i == 0)           { r = d + prv[0];      c = 2u; }
                else if (j == 0)           { r = d + prv[i - 1];  c = 1u; }
                else {
                    float cd = pp[i - 1];
                    float cu = prv[i - 1];
                    float cl = prv[i];
                    r = d + fminf(fminf(cu, cl), cd);
                    c = (cd <= cu && cd <= cl) ? 0u : ((cu <= cl) ? 1u : 2u);
                }
                cur[i] = r;
                cacc |= c << ((j & 3) * 2);
                if ((j & 3) == 3) { chb[(j >> 2) * T1 + i] = (unsigned char)cacc; cacc = 0; }
            }
            __syncthreads();
        }
    }

    {
        const int RT = T1 - SPLIT;
        for (int idx = threadIdx.x; idx < T2Q * RT; idx += blockDim.x) {
            int jq = idx / RT;
            int o  = idx - jq * RT;
            chS[idx] = chb[jq * T1 + SPLIT + o];
        }
    }
    __syncthreads();

    if (threadIdx.x == 0) {
        const int RT = T1 - SPLIT;
        int pi = T1 - 1, pj = T2 - 1;
        shi[pj] = pi;
        while (pi >= SPLIT) {
            slo[pj] = pi;
            int c = (chS[(pj >> 2) * RT + (pi - SPLIT)] >> ((pj & 3) * 2)) & 3;
            int ni = (c <= 1) ? pi - 1 : pi;
            int nj = (c != 1) ? pj - 1 : pj;
            if (nj != pj) shi[nj] = ni;
            pi = ni; pj = nj;
        }
        s_pi = pi; s_pj = pj;
    }
    __syncthreads();

    for (int idx = threadIdx.x; idx < T2Q * SPLIT; idx += blockDim.x) {
        int jq = idx / SPLIT;
        int o  = idx - jq * SPLIT;
        chS[idx] = chb[jq * T1 + o];
    }
    __syncthreads();

    if (threadIdx.x == 0) {
        int pi = s_pi, pj = s_pj;
        while (true) {
            slo[pj] = pi;
            if (pi == 0 && pj == 0) break;
            int c = (chS[(pj >> 2) * SPLIT + pi] >> ((pj & 3) * 2)) & 3;
            int ni = (c <= 1) ? pi - 1 : pi;
            int nj = (c != 1) ? pj - 1 : pj;
            if (nj != pj) shi[nj] = ni;
            pi = ni; pj = nj;
        }
    }
    __syncthreads();

    for (int j = threadIdx.x; j < T2; j += blockDim.x) {
        g_lo[b * T2 + j] = slo[j];
        g_hi[b * T2 + j] = shi[j];
    }
}

// ---------------------------------------------------------------------------
// Kernel 4: expansion — out[b][j][:] = sum_{i=lo..hi} teacher[b][i][:]
// ---------------------------------------------------------------------------
__global__ __launch_bounds__(256)
void expand_kernel(const float* __restrict__ Tt, float* __restrict__ out) {
    int j = blockIdx.x;
    int b = blockIdx.y;
    int lo = g_lo[b * T2 + j];
    int hi = g_hi[b * T2 + j];
    int d4 = threadIdx.x;
    float4 acc = make_float4(0.f, 0.f, 0.f, 0.f);
    const float4* base = (const float4*)(Tt + (size_t)b * T1 * DIM);
    for (int i2 = lo; i2 <= hi; i2++) {
        float4 v = base[(size_t)i2 * (DIM / 4) + d4];
        acc.x += v.x; acc.y += v.y; acc.z += v.z; acc.w += v.w;
    }
    ((float4*)out)[(size_t)(b * T2 + j) * (DIM / 4) + d4] = acc;
}

// ---------------------------------------------------------------------------
// Launch — kernel launches only. Profiled launch = index 3 = dtw_kernel.
// ---------------------------------------------------------------------------
extern "C" void kernel_launch(void* const* d_in, const int* in_sizes, int n_in,
                              void* d_out, int out_size) {
    const float* teacher = (const float*)d_in[0];  // [16,400,1024]
    const float* student = (const float*)d_in[1];  // [16,600,1024]
    float* out = (float*)d_out;                    // [16,600,1024]

    // 0) norms
    {
        int nwarps = NB * (T1 + T2);
        int nblocks = (nwarps + 7) / 8;
        norm_kernel<<<nblocks, 256>>>(teacher, student);
    }

    // 1) distance GEMM (row-major D)
    {
        dim3 grid((T2 + BN - 1) / BN, (T1 + BM - 1) / BM, NB);
        gemm_dist_kernel<<<grid, 256>>>(teacher, student);
    }

    // 2) transpose to diag-major
    {
        dim3 grid((T2 + 31) / 32, (T1 + 31) / 32, NB);  // 19 x 13 x 16
        transpose_diag_kernel<<<grid, 256>>>();
    }

    // 3) DTW DP + staged backtrack (profiled slot)
    dtw_kernel<<<NB, 416>>>();

    // 4) expansion
    {
        dim3 grid(T2, NB);
        expand_kernel<<<grid, 256>>>(teacher, out);
    }
}